// round 3
// baseline (speedup 1.0000x reference)
#include <cuda_runtime.h>

#define DIM 1024
#define NH 16
#define HD 64
#define TSEQ 2048
#define BT 4096          // B * T
#define SSTR 68          // padded smem row stride (floats) for attention tiles

// Scratch (static device arrays; allocation in kernel_launch is forbidden)
__device__ float g_h[BT * DIM];
__device__ float g_q[BT * DIM];
__device__ float g_k[BT * DIM];
__device__ float g_v[BT * DIM];
__device__ float g_att[BT * DIM];

// ---------------------------------------------------------------------------
// LayerNorm: one block per row of x [4096, 1024]
// ---------------------------------------------------------------------------
__global__ void ln_kernel(const float* __restrict__ x,
                          const float* __restrict__ gamma,
                          const float* __restrict__ beta,
                          float* __restrict__ out) {
    int row = blockIdx.x;
    const float* xr = x + (size_t)row * DIM;
    float* orow = out + (size_t)row * DIM;
    int t = threadIdx.x;

    float v[4];
    float sum = 0.f, sq = 0.f;
#pragma unroll
    for (int i = 0; i < 4; i++) {
        float val = xr[t + i * 256];
        v[i] = val;
        sum += val;
        sq += val * val;
    }
#pragma unroll
    for (int o = 16; o > 0; o >>= 1) {
        sum += __shfl_xor_sync(0xffffffffu, sum, o);
        sq  += __shfl_xor_sync(0xffffffffu, sq, o);
    }
    __shared__ float s1[8], s2[8];
    if ((t & 31) == 0) { s1[t >> 5] = sum; s2[t >> 5] = sq; }
    __syncthreads();
    float tot = 0.f, totq = 0.f;
#pragma unroll
    for (int i = 0; i < 8; i++) { tot += s1[i]; totq += s2[i]; }
    float mu   = tot * (1.0f / DIM);
    float var  = totq * (1.0f / DIM) - mu * mu;
    float rstd = rsqrtf(var + 1e-5f);
#pragma unroll
    for (int i = 0; i < 4; i++) {
        int c = t + i * 256;
        orow[c] = (v[i] - mu) * rstd * gamma[c] + beta[c];
    }
}

// ---------------------------------------------------------------------------
// SGEMM NT core: C[m][n] = sum_k A[m][k] * B[n][k] + bias[n]
// A: MxK row-major, B: NxK row-major. 128x128 tile, BK=16, 8x8 per thread.
// ---------------------------------------------------------------------------
__device__ __forceinline__ void gemm_nt_body(const float* __restrict__ A,
                                             const float* __restrict__ B,
                                             const float* __restrict__ bias,
                                             float* __restrict__ C,
                                             int M, int N, int K) {
    __shared__ float As[16][128];
    __shared__ float Bs[16][128];

    int tid = threadIdx.x;
    int bm = blockIdx.y * 128;
    int bn = blockIdx.x * 128;
    int tx = tid & 15;        // 0..15 -> N direction
    int ty = tid >> 4;        // 0..15 -> M direction
    int lr = tid >> 2;        // 0..63  load row
    int lc = (tid & 3) << 2;  // 0,4,8,12 load k-offset

    const float* Ap = A + (size_t)(bm + lr) * K + lc;
    const float* Bp = B + (size_t)(bn + lr) * K + lc;

    float acc[8][8];
#pragma unroll
    for (int i = 0; i < 8; i++)
#pragma unroll
        for (int j = 0; j < 8; j++) acc[i][j] = 0.f;

    for (int k0 = 0; k0 < K; k0 += 16) {
        float4 a0 = *(const float4*)(Ap + k0);
        float4 a1 = *(const float4*)(Ap + (size_t)64 * K + k0);
        float4 b0 = *(const float4*)(Bp + k0);
        float4 b1 = *(const float4*)(Bp + (size_t)64 * K + k0);
        __syncthreads();
        As[lc + 0][lr] = a0.x; As[lc + 1][lr] = a0.y;
        As[lc + 2][lr] = a0.z; As[lc + 3][lr] = a0.w;
        As[lc + 0][lr + 64] = a1.x; As[lc + 1][lr + 64] = a1.y;
        As[lc + 2][lr + 64] = a1.z; As[lc + 3][lr + 64] = a1.w;
        Bs[lc + 0][lr] = b0.x; Bs[lc + 1][lr] = b0.y;
        Bs[lc + 2][lr] = b0.z; Bs[lc + 3][lr] = b0.w;
        Bs[lc + 0][lr + 64] = b1.x; Bs[lc + 1][lr + 64] = b1.y;
        Bs[lc + 2][lr + 64] = b1.z; Bs[lc + 3][lr + 64] = b1.w;
        __syncthreads();
#pragma unroll
        for (int k = 0; k < 16; k++) {
            float ar[8], br[8];
            *(float4*)&ar[0] = *(const float4*)&As[k][ty * 8];
            *(float4*)&ar[4] = *(const float4*)&As[k][ty * 8 + 4];
            *(float4*)&br[0] = *(const float4*)&Bs[k][tx * 8];
            *(float4*)&br[4] = *(const float4*)&Bs[k][tx * 8 + 4];
#pragma unroll
            for (int i = 0; i < 8; i++)
#pragma unroll
                for (int j = 0; j < 8; j++)
                    acc[i][j] += ar[i] * br[j];
        }
    }

#pragma unroll
    for (int i = 0; i < 8; i++) {
        int row = bm + ty * 8 + i;
#pragma unroll
        for (int j = 0; j < 8; j += 4) {
            float4 o;
            o.x = acc[i][j]     + bias[bn + tx * 8 + j];
            o.y = acc[i][j + 1] + bias[bn + tx * 8 + j + 1];
            o.z = acc[i][j + 2] + bias[bn + tx * 8 + j + 2];
            o.w = acc[i][j + 3] + bias[bn + tx * 8 + j + 3];
            *(float4*)&C[(size_t)row * N + bn + tx * 8 + j] = o;
        }
    }
}

// Single GEMM (used for O-projection)
__global__ __launch_bounds__(256) void gemm_nt(const float* __restrict__ A,
                                               const float* __restrict__ B,
                                               const float* __restrict__ bias,
                                               float* __restrict__ C,
                                               int M, int N, int K) {
    gemm_nt_body(A, B, bias, C, M, N, K);
}

// Fused QKV GEMM: blockIdx.z in {0,1,2} selects weight/bias/output.
// All pointers passed as kernel arguments (graph-capture safe).
__global__ __launch_bounds__(256) void gemm_qkv(const float* __restrict__ A,
                                                const float* __restrict__ Wq,
                                                const float* __restrict__ bq,
                                                float* __restrict__ Oq,
                                                const float* __restrict__ Wk,
                                                const float* __restrict__ bk,
                                                float* __restrict__ Ok,
                                                const float* __restrict__ Wv,
                                                const float* __restrict__ bv,
                                                float* __restrict__ Ov,
                                                int M, int N, int K) {
    int z = blockIdx.z;
    const float* W = (z == 0) ? Wq : (z == 1) ? Wk : Wv;
    const float* b = (z == 0) ? bq : (z == 1) ? bk : bv;
    float* O       = (z == 0) ? Oq : (z == 1) ? Ok : Ov;
    gemm_nt_body(A, W, b, O, M, N, K);
}

// ---------------------------------------------------------------------------
// Fused causal attention (flash-style, fp32).
// Grid: (T/64, NH, B). Block: 256 threads. 64-query x 64-key tiles.
// Thread mapping: r = tid/4 (query row), g = tid%4 (column/dim group).
// Key columns per thread: c = g + 4*i (interleaved -> conflict-free sK reads).
// Output dims per thread: d = g*16 .. g*16+15.
// ---------------------------------------------------------------------------
__global__ __launch_bounds__(256) void attn_kernel(const float* __restrict__ Q,
                                                   const float* __restrict__ K,
                                                   const float* __restrict__ V,
                                                   float* __restrict__ O) {
    extern __shared__ float smem[];
    float* sQ = smem;                  // 64 * SSTR
    float* sK = sQ + 64 * SSTR;
    float* sV = sK + 64 * SSTR;
    float* sP = sV + 64 * SSTR;

    int tid = threadIdx.x;
    int r = tid >> 2;
    int g = tid & 3;
    int qblk = blockIdx.x;
    int h = blockIdx.y;
    int b = blockIdx.z;
    int q0 = qblk * 64;
    size_t base = ((size_t)b * TSEQ) * DIM + h * HD;

    int lr = tid >> 2;          // load row (0..63)
    int lc = (tid & 3) * 16;    // load dim offset

    // Load Q tile once
    {
        const float* src = Q + base + (size_t)(q0 + lr) * DIM + lc;
        float* dst = sQ + lr * SSTR + lc;
#pragma unroll
        for (int j = 0; j < 4; j++)
            *(float4*)(dst + 4 * j) = *(const float4*)(src + 4 * j);
    }

    float o[16];
#pragma unroll
    for (int i = 0; i < 16; i++) o[i] = 0.f;
    float m = -1e30f, l = 0.f;

    for (int kb = 0; kb <= qblk; kb++) {
        __syncthreads();  // previous iter's smem reads done before overwrite
        {
            const float* ks = K + base + (size_t)(kb * 64 + lr) * DIM + lc;
            const float* vs = V + base + (size_t)(kb * 64 + lr) * DIM + lc;
            float* kd = sK + lr * SSTR + lc;
            float* vd = sV + lr * SSTR + lc;
#pragma unroll
            for (int j = 0; j < 4; j++) {
                *(float4*)(kd + 4 * j) = *(const float4*)(ks + 4 * j);
                *(float4*)(vd + 4 * j) = *(const float4*)(vs + 4 * j);
            }
        }
        __syncthreads();

        // S = (Q K^T) * 1/sqrt(Dh), thread handles cols c = g + 4*i
        float s[16];
        const float4* q4 = (const float4*)(sQ + r * SSTR);
#pragma unroll
        for (int i = 0; i < 16; i++) {
            const float4* k4 = (const float4*)(sK + (g + 4 * i) * SSTR);
            float acc = 0.f;
#pragma unroll
            for (int d = 0; d < 16; d++) {
                float4 qq = q4[d];
                float4 kk = k4[d];
                acc += qq.x * kk.x;
                acc += qq.y * kk.y;
                acc += qq.z * kk.z;
                acc += qq.w * kk.w;
            }
            s[i] = acc * 0.125f;
        }
        if (kb == qblk) {
#pragma unroll
            for (int i = 0; i < 16; i++)
                if (g + 4 * i > r) s[i] = -1e30f;
        }

        // Online softmax (4-thread row group reduction via shfl)
        float mloc = s[0];
#pragma unroll
        for (int i = 1; i < 16; i++) mloc = fmaxf(mloc, s[i]);
        mloc = fmaxf(mloc, __shfl_xor_sync(0xffffffffu, mloc, 1));
        mloc = fmaxf(mloc, __shfl_xor_sync(0xffffffffu, mloc, 2));
        float mnew = fmaxf(m, mloc);
        float corr = __expf(m - mnew);
        float psum = 0.f;
#pragma unroll
        for (int i = 0; i < 16; i++) {
            float p = __expf(s[i] - mnew);
            s[i] = p;
            psum += p;
        }
        psum += __shfl_xor_sync(0xffffffffu, psum, 1);
        psum += __shfl_xor_sync(0xffffffffu, psum, 2);
        l = l * corr + psum;
        m = mnew;
#pragma unroll
        for (int i = 0; i < 16; i++) o[i] *= corr;

        // Share P through smem
#pragma unroll
        for (int i = 0; i < 16; i++)
            sP[r * SSTR + g + 4 * i] = s[i];
        __syncthreads();

        // O += P V  (thread dims d = g*16 + 0..15)
#pragma unroll 4
        for (int c = 0; c < 64; c++) {
            float p = sP[r * SSTR + c];
            const float4* v4 = (const float4*)(sV + c * SSTR + g * 16);
#pragma unroll
            for (int j = 0; j < 4; j++) {
                float4 vv = v4[j];
                o[4 * j + 0] += p * vv.x;
                o[4 * j + 1] += p * vv.y;
                o[4 * j + 2] += p * vv.z;
                o[4 * j + 3] += p * vv.w;
            }
        }
    }

    float inv = 1.0f / l;
    float* dst = O + base + (size_t)(q0 + r) * DIM + g * 16;
#pragma unroll
    for (int j = 0; j < 4; j++) {
        float4 ov;
        ov.x = o[4 * j + 0] * inv;
        ov.y = o[4 * j + 1] * inv;
        ov.z = o[4 * j + 2] * inv;
        ov.w = o[4 * j + 3] * inv;
        *(float4*)(dst + 4 * j) = ov;
    }
}

// ---------------------------------------------------------------------------
extern "C" void kernel_launch(void* const* d_in, const int* in_sizes, int n_in,
                              void* d_out, int out_size) {
    const float* x  = (const float*)d_in[0];
    const float* g1 = (const float*)d_in[1];
    const float* b1 = (const float*)d_in[2];
    const float* Wq = (const float*)d_in[3];
    const float* bq = (const float*)d_in[4];
    const float* Wk = (const float*)d_in[5];
    const float* bk = (const float*)d_in[6];
    const float* Wv = (const float*)d_in[7];
    const float* bv = (const float*)d_in[8];
    const float* Wo = (const float*)d_in[9];
    const float* bo = (const float*)d_in[10];
    float* out = (float*)d_out;

    float *h_p, *q_p, *k_p, *v_p, *a_p;
    cudaGetSymbolAddress((void**)&h_p, g_h);
    cudaGetSymbolAddress((void**)&q_p, g_q);
    cudaGetSymbolAddress((void**)&k_p, g_k);
    cudaGetSymbolAddress((void**)&v_p, g_v);
    cudaGetSymbolAddress((void**)&a_p, g_att);

    const int attn_smem = 4 * 64 * SSTR * (int)sizeof(float);  // 69632 B
    cudaFuncSetAttribute(attn_kernel, cudaFuncAttributeMaxDynamicSharedMemorySize,
                         attn_smem);

    ln_kernel<<<BT, 256>>>(x, g1, b1, h_p);

    dim3 qkv_grid(DIM / 128, BT / 128, 3);
    gemm_qkv<<<qkv_grid, 256>>>(h_p, Wq, bq, q_p, Wk, bk, k_p, Wv, bv, v_p,
                                BT, DIM, DIM);

    attn_kernel<<<dim3(TSEQ / 64, NH, 2), 256, attn_smem>>>(q_p, k_p, v_p, a_p);

    dim3 ggrid(DIM / 128, BT / 128);
    gemm_nt<<<ggrid, 256>>>(a_p, Wo, bo, out, BT, DIM, DIM);
}

// round 4
// speedup vs baseline: 2.7548x; 2.7548x over previous
#include <cuda_runtime.h>
#include <cstdint>

#define DIM 1024
#define NH 16
#define HD 64
#define TSEQ 2048
#define BT 4096          // B * T
#define ASTR 66          // attention smem stride (floats): 66 mod 32 = 2 -> conflict-free float2
#define GSTR 20          // gemm smem stride (words): conflict-free for tf32 frag loads

// Scratch (static device arrays; allocation in kernel_launch is forbidden)
__device__ float g_h[BT * DIM];
__device__ float g_q[BT * DIM];
__device__ float g_k[BT * DIM];
__device__ float g_v[BT * DIM];
__device__ float g_att[BT * DIM];

// ---------------------------------------------------------------------------
// LayerNorm: one block per row of x [4096, 1024]
// ---------------------------------------------------------------------------
__global__ void ln_kernel(const float* __restrict__ x,
                          const float* __restrict__ gamma,
                          const float* __restrict__ beta,
                          float* __restrict__ out) {
    int row = blockIdx.x;
    const float* xr = x + (size_t)row * DIM;
    float* orow = out + (size_t)row * DIM;
    int t = threadIdx.x;

    float v[4];
    float sum = 0.f, sq = 0.f;
#pragma unroll
    for (int i = 0; i < 4; i++) {
        float val = xr[t + i * 256];
        v[i] = val;
        sum += val;
        sq += val * val;
    }
#pragma unroll
    for (int o = 16; o > 0; o >>= 1) {
        sum += __shfl_xor_sync(0xffffffffu, sum, o);
        sq  += __shfl_xor_sync(0xffffffffu, sq, o);
    }
    __shared__ float s1[8], s2[8];
    if ((t & 31) == 0) { s1[t >> 5] = sum; s2[t >> 5] = sq; }
    __syncthreads();
    float tot = 0.f, totq = 0.f;
#pragma unroll
    for (int i = 0; i < 8; i++) { tot += s1[i]; totq += s2[i]; }
    float mu   = tot * (1.0f / DIM);
    float var  = totq * (1.0f / DIM) - mu * mu;
    float rstd = rsqrtf(var + 1e-5f);
#pragma unroll
    for (int i = 0; i < 4; i++) {
        int c = t + i * 256;
        orow[c] = (v[i] - mu) * rstd * gamma[c] + beta[c];
    }
}

// ---------------------------------------------------------------------------
// tf32 helpers
// ---------------------------------------------------------------------------
__device__ __forceinline__ uint32_t f2tf(float x) {
    uint32_t y;
    asm("cvt.rna.tf32.f32 %0, %1;" : "=r"(y) : "f"(x));
    return y;
}

__device__ __forceinline__ void mma_tf32(float* c, const uint32_t* a,
                                         const uint32_t* b) {
    asm volatile(
        "mma.sync.aligned.m16n8k8.row.col.f32.tf32.tf32.f32 "
        "{%0,%1,%2,%3}, {%4,%5,%6,%7}, {%8,%9}, {%0,%1,%2,%3};\n"
        : "+f"(c[0]), "+f"(c[1]), "+f"(c[2]), "+f"(c[3])
        : "r"(a[0]), "r"(a[1]), "r"(a[2]), "r"(a[3]), "r"(b[0]), "r"(b[1]));
}

// ---------------------------------------------------------------------------
// tf32 GEMM NT: C[m][n] = sum_k A[m][k]*B[n][k] + bias[n]
// 128x128 tile, BK=16, 256 threads = 8 warps (2 m x 4 n), warp tile 64x32.
// As/Bs stored [row][k] stride GSTR=20 words (conflict-free frag loads).
// ---------------------------------------------------------------------------
__device__ __forceinline__ void gemm_tf32_body(const float* __restrict__ A,
                                               const float* __restrict__ B,
                                               const float* __restrict__ bias,
                                               float* __restrict__ C,
                                               int M, int N, int K) {
    __shared__ uint32_t As[128 * GSTR];
    __shared__ uint32_t Bs[128 * GSTR];

    int tid = threadIdx.x;
    int bm = blockIdx.y * 128;
    int bn = blockIdx.x * 128;
    int w = tid >> 5, lane = tid & 31;
    int wm = (w & 1) * 64;        // warp m offset
    int wn = (w >> 1) * 32;       // warp n offset
    int lq = lane >> 2;           // lane/4
    int lrm = lane & 3;           // lane%4
    int lr = tid >> 2;            // load row 0..63
    int lc = (tid & 3) << 2;      // load k offset 0,4,8,12

    const float* Ap = A + (size_t)(bm + lr) * K + lc;
    const float* Bp = B + (size_t)(bn + lr) * K + lc;

    float acc[4][4][4];
#pragma unroll
    for (int mi = 0; mi < 4; mi++)
#pragma unroll
        for (int ni = 0; ni < 4; ni++)
#pragma unroll
            for (int r = 0; r < 4; r++) acc[mi][ni][r] = 0.f;

    for (int k0 = 0; k0 < K; k0 += 16) {
        float4 a0 = *(const float4*)(Ap + k0);
        float4 a1 = *(const float4*)(Ap + (size_t)64 * K + k0);
        float4 b0 = *(const float4*)(Bp + k0);
        float4 b1 = *(const float4*)(Bp + (size_t)64 * K + k0);
        __syncthreads();
        {
            uint4 u;
            u.x = f2tf(a0.x); u.y = f2tf(a0.y); u.z = f2tf(a0.z); u.w = f2tf(a0.w);
            *(uint4*)&As[lr * GSTR + lc] = u;
            u.x = f2tf(a1.x); u.y = f2tf(a1.y); u.z = f2tf(a1.z); u.w = f2tf(a1.w);
            *(uint4*)&As[(lr + 64) * GSTR + lc] = u;
            u.x = f2tf(b0.x); u.y = f2tf(b0.y); u.z = f2tf(b0.z); u.w = f2tf(b0.w);
            *(uint4*)&Bs[lr * GSTR + lc] = u;
            u.x = f2tf(b1.x); u.y = f2tf(b1.y); u.z = f2tf(b1.z); u.w = f2tf(b1.w);
            *(uint4*)&Bs[(lr + 64) * GSTR + lc] = u;
        }
        __syncthreads();

#pragma unroll
        for (int ks = 0; ks < 16; ks += 8) {
            uint32_t af[4][4], bf[4][2];
#pragma unroll
            for (int mi = 0; mi < 4; mi++) {
                int rowA = wm + mi * 16;
                af[mi][0] = As[(rowA + lq) * GSTR + ks + lrm];
                af[mi][1] = As[(rowA + lq + 8) * GSTR + ks + lrm];
                af[mi][2] = As[(rowA + lq) * GSTR + ks + lrm + 4];
                af[mi][3] = As[(rowA + lq + 8) * GSTR + ks + lrm + 4];
            }
#pragma unroll
            for (int ni = 0; ni < 4; ni++) {
                int rowB = wn + ni * 8;
                bf[ni][0] = Bs[(rowB + lq) * GSTR + ks + lrm];
                bf[ni][1] = Bs[(rowB + lq) * GSTR + ks + lrm + 4];
            }
#pragma unroll
            for (int mi = 0; mi < 4; mi++)
#pragma unroll
                for (int ni = 0; ni < 4; ni++)
                    mma_tf32(acc[mi][ni], af[mi], bf[ni]);
        }
    }

    // Epilogue: C row = bm+wm+mi*16+lq (+8), col = bn+wn+ni*8+lrm*2 (+1)
#pragma unroll
    for (int mi = 0; mi < 4; mi++) {
#pragma unroll
        for (int ni = 0; ni < 4; ni++) {
            int row0 = bm + wm + mi * 16 + lq;
            int col  = bn + wn + ni * 8 + lrm * 2;
            float2 bb = *(const float2*)&bias[col];
            float2 o0, o1;
            o0.x = acc[mi][ni][0] + bb.x;
            o0.y = acc[mi][ni][1] + bb.y;
            o1.x = acc[mi][ni][2] + bb.x;
            o1.y = acc[mi][ni][3] + bb.y;
            *(float2*)&C[(size_t)row0 * N + col] = o0;
            *(float2*)&C[(size_t)(row0 + 8) * N + col] = o1;
        }
    }
}

// Single GEMM (O-projection)
__global__ __launch_bounds__(256) void gemm_tf32(const float* __restrict__ A,
                                                 const float* __restrict__ B,
                                                 const float* __restrict__ bias,
                                                 float* __restrict__ C,
                                                 int M, int N, int K) {
    gemm_tf32_body(A, B, bias, C, M, N, K);
}

// Fused QKV GEMM: blockIdx.z selects weight/bias/output (args, capture-safe)
__global__ __launch_bounds__(256) void gemm_qkv(const float* __restrict__ A,
                                                const float* __restrict__ Wq,
                                                const float* __restrict__ bq,
                                                float* __restrict__ Oq,
                                                const float* __restrict__ Wk,
                                                const float* __restrict__ bk,
                                                float* __restrict__ Ok,
                                                const float* __restrict__ Wv,
                                                const float* __restrict__ bv,
                                                float* __restrict__ Ov,
                                                int M, int N, int K) {
    int z = blockIdx.z;
    const float* W = (z == 0) ? Wq : (z == 1) ? Wk : Wv;
    const float* b = (z == 0) ? bq : (z == 1) ? bk : bv;
    float* O       = (z == 0) ? Oq : (z == 1) ? Ok : Ov;
    gemm_tf32_body(A, W, b, O, M, N, K);
}

// ---------------------------------------------------------------------------
// Fused causal attention (flash-style, fp32), 4x4 register blocked.
// Grid: (T/64, NH, B). Block: 256 threads. 64-query x 64-key tiles.
// Thread t: rg=t/16 -> q rows rg*4..rg*4+3; cg=t%16.
//   S phase cols: c = cg + 16*j (j=0..3), float2 d-loop (conflict-free, ASTR=66)
//   PV phase dims: d = jj*32 + cg*2 + {0,1}
// ---------------------------------------------------------------------------
__global__ __launch_bounds__(256) void attn_kernel(const float* __restrict__ Q,
                                                   const float* __restrict__ K,
                                                   const float* __restrict__ V,
                                                   float* __restrict__ O) {
    extern __shared__ float smem[];
    float* sQ = smem;                  // 64 * ASTR
    float* sK = sQ + 64 * ASTR;
    float* sV = sK + 64 * ASTR;
    float* sP = sV + 64 * ASTR;

    int tid = threadIdx.x;
    int rg = tid >> 4;          // 0..15
    int cg = tid & 15;          // 0..15
    int r0 = rg * 4;
    int qblk = blockIdx.x;
    int h = blockIdx.y;
    int b = blockIdx.z;
    int q0 = qblk * 64;
    size_t base = ((size_t)b * TSEQ) * DIM + h * HD;

    int lr = tid >> 2;          // load row (0..63)
    int lc = (tid & 3) * 16;    // load dim offset

    // Load Q tile once (float4 gmem reads, scalar smem stores; stride 66)
    {
        const float* src = Q + base + (size_t)(q0 + lr) * DIM + lc;
        float* dst = sQ + lr * ASTR + lc;
#pragma unroll
        for (int j = 0; j < 4; j++) {
            float4 t4 = *(const float4*)(src + 4 * j);
            dst[4 * j + 0] = t4.x; dst[4 * j + 1] = t4.y;
            dst[4 * j + 2] = t4.z; dst[4 * j + 3] = t4.w;
        }
    }

    float o[4][4];
#pragma unroll
    for (int i = 0; i < 4; i++)
#pragma unroll
        for (int j = 0; j < 4; j++) o[i][j] = 0.f;
    float m[4], l[4];
#pragma unroll
    for (int i = 0; i < 4; i++) { m[i] = -1e30f; l[i] = 0.f; }

    for (int kb = 0; kb <= qblk; kb++) {
        __syncthreads();  // prior iter's smem reads done before overwrite
        {
            const float* ks = K + base + (size_t)(kb * 64 + lr) * DIM + lc;
            const float* vs = V + base + (size_t)(kb * 64 + lr) * DIM + lc;
            float* kd = sK + lr * ASTR + lc;
            float* vd = sV + lr * ASTR + lc;
#pragma unroll
            for (int j = 0; j < 4; j++) {
                float4 kt = *(const float4*)(ks + 4 * j);
                float4 vt = *(const float4*)(vs + 4 * j);
                kd[4 * j + 0] = kt.x; kd[4 * j + 1] = kt.y;
                kd[4 * j + 2] = kt.z; kd[4 * j + 3] = kt.w;
                vd[4 * j + 0] = vt.x; vd[4 * j + 1] = vt.y;
                vd[4 * j + 2] = vt.z; vd[4 * j + 3] = vt.w;
            }
        }
        __syncthreads();

        // ---- S = Q K^T (4 rows x 4 cols per thread) ----
        float s[4][4];
#pragma unroll
        for (int i = 0; i < 4; i++)
#pragma unroll
            for (int j = 0; j < 4; j++) s[i][j] = 0.f;

#pragma unroll 8
        for (int dd = 0; dd < 32; dd++) {
            float2 kk[4];
#pragma unroll
            for (int j = 0; j < 4; j++)
                kk[j] = *(const float2*)(sK + (cg + 16 * j) * ASTR + dd * 2);
#pragma unroll
            for (int i = 0; i < 4; i++) {
                float2 qq = *(const float2*)(sQ + (r0 + i) * ASTR + dd * 2);
#pragma unroll
                for (int j = 0; j < 4; j++) {
                    s[i][j] += qq.x * kk[j].x;
                    s[i][j] += qq.y * kk[j].y;
                }
            }
        }
#pragma unroll
        for (int i = 0; i < 4; i++)
#pragma unroll
            for (int j = 0; j < 4; j++) s[i][j] *= 0.125f;

        if (kb == qblk) {
#pragma unroll
            for (int i = 0; i < 4; i++)
#pragma unroll
                for (int j = 0; j < 4; j++)
                    if (cg + 16 * j > r0 + i) s[i][j] = -1e30f;
        }

        // ---- online softmax per row (reduce across the 16-lane col group) ----
#pragma unroll
        for (int i = 0; i < 4; i++) {
            float mloc = fmaxf(fmaxf(s[i][0], s[i][1]), fmaxf(s[i][2], s[i][3]));
            mloc = fmaxf(mloc, __shfl_xor_sync(0xffffffffu, mloc, 1));
            mloc = fmaxf(mloc, __shfl_xor_sync(0xffffffffu, mloc, 2));
            mloc = fmaxf(mloc, __shfl_xor_sync(0xffffffffu, mloc, 4));
            mloc = fmaxf(mloc, __shfl_xor_sync(0xffffffffu, mloc, 8));
            float mnew = fmaxf(m[i], mloc);
            float corr = __expf(m[i] - mnew);
            float psum = 0.f;
#pragma unroll
            for (int j = 0; j < 4; j++) {
                float p = __expf(s[i][j] - mnew);
                s[i][j] = p;
                psum += p;
            }
            psum += __shfl_xor_sync(0xffffffffu, psum, 1);
            psum += __shfl_xor_sync(0xffffffffu, psum, 2);
            psum += __shfl_xor_sync(0xffffffffu, psum, 4);
            psum += __shfl_xor_sync(0xffffffffu, psum, 8);
            l[i] = l[i] * corr + psum;
            m[i] = mnew;
#pragma unroll
            for (int j = 0; j < 4; j++) o[i][j] *= corr;
        }

        // share P through smem
#pragma unroll
        for (int i = 0; i < 4; i++)
#pragma unroll
            for (int j = 0; j < 4; j++)
                sP[(r0 + i) * ASTR + cg + 16 * j] = s[i][j];
        __syncthreads();

        // ---- O += P V (4 rows x 4 dims per thread) ----
#pragma unroll 4
        for (int c = 0; c < 64; c++) {
            float p[4];
#pragma unroll
            for (int i = 0; i < 4; i++) p[i] = sP[(r0 + i) * ASTR + c];
            float2 v0 = *(const float2*)(sV + c * ASTR + cg * 2);
            float2 v1 = *(const float2*)(sV + c * ASTR + 32 + cg * 2);
#pragma unroll
            for (int i = 0; i < 4; i++) {
                o[i][0] += p[i] * v0.x;
                o[i][1] += p[i] * v0.y;
                o[i][2] += p[i] * v1.x;
                o[i][3] += p[i] * v1.y;
            }
        }
    }

    // ---- write out ----
#pragma unroll
    for (int i = 0; i < 4; i++) {
        float inv = 1.0f / l[i];
        float* dst = O + base + (size_t)(q0 + r0 + i) * DIM;
        float2 w0, w1;
        w0.x = o[i][0] * inv; w0.y = o[i][1] * inv;
        w1.x = o[i][2] * inv; w1.y = o[i][3] * inv;
        *(float2*)(dst + cg * 2) = w0;
        *(float2*)(dst + 32 + cg * 2) = w1;
    }
}

// ---------------------------------------------------------------------------
extern "C" void kernel_launch(void* const* d_in, const int* in_sizes, int n_in,
                              void* d_out, int out_size) {
    const float* x  = (const float*)d_in[0];
    const float* g1 = (const float*)d_in[1];
    const float* b1 = (const float*)d_in[2];
    const float* Wq = (const float*)d_in[3];
    const float* bq = (const float*)d_in[4];
    const float* Wk = (const float*)d_in[5];
    const float* bk = (const float*)d_in[6];
    const float* Wv = (const float*)d_in[7];
    const float* bv = (const float*)d_in[8];
    const float* Wo = (const float*)d_in[9];
    const float* bo = (const float*)d_in[10];
    float* out = (float*)d_out;

    float *h_p, *q_p, *k_p, *v_p, *a_p;
    cudaGetSymbolAddress((void**)&h_p, g_h);
    cudaGetSymbolAddress((void**)&q_p, g_q);
    cudaGetSymbolAddress((void**)&k_p, g_k);
    cudaGetSymbolAddress((void**)&v_p, g_v);
    cudaGetSymbolAddress((void**)&a_p, g_att);

    const int attn_smem = 4 * 64 * ASTR * (int)sizeof(float);  // 67584 B
    cudaFuncSetAttribute(attn_kernel, cudaFuncAttributeMaxDynamicSharedMemorySize,
                         attn_smem);

    ln_kernel<<<BT, 256>>>(x, g1, b1, h_p);

    dim3 qkv_grid(DIM / 128, BT / 128, 3);
    gemm_qkv<<<qkv_grid, 256>>>(h_p, Wq, bq, q_p, Wk, bk, k_p, Wv, bv, v_p,
                                BT, DIM, DIM);

    attn_kernel<<<dim3(TSEQ / 64, NH, 2), 256, attn_smem>>>(q_p, k_p, v_p, a_p);

    dim3 ggrid(DIM / 128, BT / 128);
    gemm_tf32<<<ggrid, 256>>>(a_p, Wo, bo, out, BT, DIM, DIM);
}

// round 6
// speedup vs baseline: 3.9718x; 1.4418x over previous
#include <cuda_runtime.h>
#include <cstdint>

#define DIM 1024
#define NH 16
#define HD 64
#define TSEQ 2048
#define BT 4096          // B * T
#define GSTR 20          // gemm smem stride (words): conflict-free for tf32 frag loads
#define FSTR 68          // attention smem stride (words): 68 mod 32 = 4 -> frag loads conflict-free

// Scratch (static device arrays; allocation in kernel_launch is forbidden)
__device__ float g_h[BT * DIM];
__device__ float g_q[BT * DIM];
__device__ float g_k[BT * DIM];
__device__ float g_v[BT * DIM];
__device__ float g_att[BT * DIM];

// ---------------------------------------------------------------------------
// LayerNorm: one block per row of x [4096, 1024]
// ---------------------------------------------------------------------------
__global__ void ln_kernel(const float* __restrict__ x,
                          const float* __restrict__ gamma,
                          const float* __restrict__ beta,
                          float* __restrict__ out) {
    int row = blockIdx.x;
    const float* xr = x + (size_t)row * DIM;
    float* orow = out + (size_t)row * DIM;
    int t = threadIdx.x;

    float v[4];
    float sum = 0.f, sq = 0.f;
#pragma unroll
    for (int i = 0; i < 4; i++) {
        float val = xr[t + i * 256];
        v[i] = val;
        sum += val;
        sq += val * val;
    }
#pragma unroll
    for (int o = 16; o > 0; o >>= 1) {
        sum += __shfl_xor_sync(0xffffffffu, sum, o);
        sq  += __shfl_xor_sync(0xffffffffu, sq, o);
    }
    __shared__ float s1[8], s2[8];
    if ((t & 31) == 0) { s1[t >> 5] = sum; s2[t >> 5] = sq; }
    __syncthreads();
    float tot = 0.f, totq = 0.f;
#pragma unroll
    for (int i = 0; i < 8; i++) { tot += s1[i]; totq += s2[i]; }
    float mu   = tot * (1.0f / DIM);
    float var  = totq * (1.0f / DIM) - mu * mu;
    float rstd = rsqrtf(var + 1e-5f);
#pragma unroll
    for (int i = 0; i < 4; i++) {
        int c = t + i * 256;
        orow[c] = (v[i] - mu) * rstd * gamma[c] + beta[c];
    }
}

// ---------------------------------------------------------------------------
// tf32 helpers
// ---------------------------------------------------------------------------
__device__ __forceinline__ uint32_t f2tf(float x) {
    uint32_t y;
    asm("cvt.rna.tf32.f32 %0, %1;" : "=r"(y) : "f"(x));
    return y;
}

__device__ __forceinline__ void mma_tf32(float* c, const uint32_t* a,
                                         const uint32_t* b) {
    asm volatile(
        "mma.sync.aligned.m16n8k8.row.col.f32.tf32.tf32.f32 "
        "{%0,%1,%2,%3}, {%4,%5,%6,%7}, {%8,%9}, {%0,%1,%2,%3};\n"
        : "+f"(c[0]), "+f"(c[1]), "+f"(c[2]), "+f"(c[3])
        : "r"(a[0]), "r"(a[1]), "r"(a[2]), "r"(a[3]), "r"(b[0]), "r"(b[1]));
}

// ---------------------------------------------------------------------------
// tf32 GEMM NT: C[m][n] = sum_k A[m][k]*B[n][k] + bias[n]
// 128x128 tile, BK=16, 256 threads = 8 warps (2 m x 4 n), warp tile 64x32.
// ---------------------------------------------------------------------------
__device__ __forceinline__ void gemm_tf32_body(const float* __restrict__ A,
                                               const float* __restrict__ B,
                                               const float* __restrict__ bias,
                                               float* __restrict__ C,
                                               int M, int N, int K) {
    __shared__ uint32_t As[128 * GSTR];
    __shared__ uint32_t Bs[128 * GSTR];

    int tid = threadIdx.x;
    int bm = blockIdx.y * 128;
    int bn = blockIdx.x * 128;
    int w = tid >> 5, lane = tid & 31;
    int wm = (w & 1) * 64;        // warp m offset
    int wn = (w >> 1) * 32;       // warp n offset
    int lq = lane >> 2;           // lane/4
    int lrm = lane & 3;           // lane%4
    int lr = tid >> 2;            // load row 0..63
    int lc = (tid & 3) << 2;      // load k offset 0,4,8,12

    const float* Ap = A + (size_t)(bm + lr) * K + lc;
    const float* Bp = B + (size_t)(bn + lr) * K + lc;

    float acc[4][4][4];
#pragma unroll
    for (int mi = 0; mi < 4; mi++)
#pragma unroll
        for (int ni = 0; ni < 4; ni++)
#pragma unroll
            for (int r = 0; r < 4; r++) acc[mi][ni][r] = 0.f;

    for (int k0 = 0; k0 < K; k0 += 16) {
        float4 a0 = *(const float4*)(Ap + k0);
        float4 a1 = *(const float4*)(Ap + (size_t)64 * K + k0);
        float4 b0 = *(const float4*)(Bp + k0);
        float4 b1 = *(const float4*)(Bp + (size_t)64 * K + k0);
        __syncthreads();
        {
            uint4 u;
            u.x = f2tf(a0.x); u.y = f2tf(a0.y); u.z = f2tf(a0.z); u.w = f2tf(a0.w);
            *(uint4*)&As[lr * GSTR + lc] = u;
            u.x = f2tf(a1.x); u.y = f2tf(a1.y); u.z = f2tf(a1.z); u.w = f2tf(a1.w);
            *(uint4*)&As[(lr + 64) * GSTR + lc] = u;
            u.x = f2tf(b0.x); u.y = f2tf(b0.y); u.z = f2tf(b0.z); u.w = f2tf(b0.w);
            *(uint4*)&Bs[lr * GSTR + lc] = u;
            u.x = f2tf(b1.x); u.y = f2tf(b1.y); u.z = f2tf(b1.z); u.w = f2tf(b1.w);
            *(uint4*)&Bs[(lr + 64) * GSTR + lc] = u;
        }
        __syncthreads();

#pragma unroll
        for (int ks = 0; ks < 16; ks += 8) {
            uint32_t af[4][4], bf[4][2];
#pragma unroll
            for (int mi = 0; mi < 4; mi++) {
                int rowA = wm + mi * 16;
                af[mi][0] = As[(rowA + lq) * GSTR + ks + lrm];
                af[mi][1] = As[(rowA + lq + 8) * GSTR + ks + lrm];
                af[mi][2] = As[(rowA + lq) * GSTR + ks + lrm + 4];
                af[mi][3] = As[(rowA + lq + 8) * GSTR + ks + lrm + 4];
            }
#pragma unroll
            for (int ni = 0; ni < 4; ni++) {
                int rowB = wn + ni * 8;
                bf[ni][0] = Bs[(rowB + lq) * GSTR + ks + lrm];
                bf[ni][1] = Bs[(rowB + lq) * GSTR + ks + lrm + 4];
            }
#pragma unroll
            for (int mi = 0; mi < 4; mi++)
#pragma unroll
                for (int ni = 0; ni < 4; ni++)
                    mma_tf32(acc[mi][ni], af[mi], bf[ni]);
        }
    }

#pragma unroll
    for (int mi = 0; mi < 4; mi++) {
#pragma unroll
        for (int ni = 0; ni < 4; ni++) {
            int row0 = bm + wm + mi * 16 + lq;
            int col  = bn + wn + ni * 8 + lrm * 2;
            float2 bb = *(const float2*)&bias[col];
            float2 o0, o1;
            o0.x = acc[mi][ni][0] + bb.x;
            o0.y = acc[mi][ni][1] + bb.y;
            o1.x = acc[mi][ni][2] + bb.x;
            o1.y = acc[mi][ni][3] + bb.y;
            *(float2*)&C[(size_t)row0 * N + col] = o0;
            *(float2*)&C[(size_t)(row0 + 8) * N + col] = o1;
        }
    }
}

// Single GEMM (O-projection)
__global__ __launch_bounds__(256) void gemm_tf32(const float* __restrict__ A,
                                                 const float* __restrict__ B,
                                                 const float* __restrict__ bias,
                                                 float* __restrict__ C,
                                                 int M, int N, int K) {
    gemm_tf32_body(A, B, bias, C, M, N, K);
}

// Fused QKV GEMM: blockIdx.z selects weight/bias/output (args, capture-safe)
__global__ __launch_bounds__(256) void gemm_qkv(const float* __restrict__ A,
                                                const float* __restrict__ Wq,
                                                const float* __restrict__ bq,
                                                float* __restrict__ Oq,
                                                const float* __restrict__ Wk,
                                                const float* __restrict__ bk,
                                                float* __restrict__ Ok,
                                                const float* __restrict__ Wv,
                                                const float* __restrict__ bv,
                                                float* __restrict__ Ov,
                                                int M, int N, int K) {
    int z = blockIdx.z;
    const float* W = (z == 0) ? Wq : (z == 1) ? Wk : Wv;
    const float* b = (z == 0) ? bq : (z == 1) ? bk : bv;
    float* O       = (z == 0) ? Oq : (z == 1) ? Ok : Ov;
    gemm_tf32_body(A, W, b, O, M, N, K);
}

// ---------------------------------------------------------------------------
// Tensor-core causal flash attention (tf32 mma, fp32 accum/softmax).
// Grid: (T/64, NH, B). Block: 128 threads = 4 warps; warp w owns q rows
// [16w, 16w+16). 64x64 tiles. S and PV via mma.sync.m16n8k8.
// smem: sQ, sK, sVt (V transposed: [d][key]), sP — all tf32, stride FSTR=68.
// ---------------------------------------------------------------------------
__global__ __launch_bounds__(128) void attn_kernel(const float* __restrict__ Q,
                                                   const float* __restrict__ K,
                                                   const float* __restrict__ V,
                                                   float* __restrict__ O) {
    extern __shared__ uint32_t sm[];
    uint32_t* sQ  = sm;                 // 64*FSTR
    uint32_t* sK  = sQ + 64 * FSTR;
    uint32_t* sVt = sK + 64 * FSTR;     // sVt[d*FSTR + key]
    uint32_t* sP  = sVt + 64 * FSTR;

    int tid = threadIdx.x;
    int w = tid >> 5, lane = tid & 31;
    int lq = lane >> 2, lrm = lane & 3;
    int rowA = w * 16;
    int qblk = blockIdx.x;
    int h = blockIdx.y;
    int b = blockIdx.z;
    int q0 = qblk * 64;
    size_t base = ((size_t)b * TSEQ) * DIM + h * HD;

    int lr = tid >> 1;            // load row 0..63
    int lc = (tid & 1) * 32;      // load col offset 0/32

    // Load Q tile once (as tf32)
    {
        const float* src = Q + base + (size_t)(q0 + lr) * DIM + lc;
        uint32_t* dst = sQ + lr * FSTR + lc;
#pragma unroll
        for (int i = 0; i < 8; i++) {
            float4 t4 = *(const float4*)(src + 4 * i);
            dst[4 * i + 0] = f2tf(t4.x); dst[4 * i + 1] = f2tf(t4.y);
            dst[4 * i + 2] = f2tf(t4.z); dst[4 * i + 3] = f2tf(t4.w);
        }
    }

    float o_frag[8][4];
#pragma unroll
    for (int n = 0; n < 8; n++)
#pragma unroll
        for (int r = 0; r < 4; r++) o_frag[n][r] = 0.f;
    float m0 = -1e30f, m1 = -1e30f, l0 = 0.f, l1 = 0.f;

    for (int kb = 0; kb <= qblk; kb++) {
        __syncthreads();  // all warps done with prior sK/sVt before refill
        {
            const float* ksrc = K + base + (size_t)(kb * 64 + lr) * DIM + lc;
            const float* vsrc = V + base + (size_t)(kb * 64 + lr) * DIM + lc;
            uint32_t* kd = sK + lr * FSTR + lc;
#pragma unroll
            for (int i = 0; i < 8; i++) {
                float4 kt = *(const float4*)(ksrc + 4 * i);
                kd[4 * i + 0] = f2tf(kt.x); kd[4 * i + 1] = f2tf(kt.y);
                kd[4 * i + 2] = f2tf(kt.z); kd[4 * i + 3] = f2tf(kt.w);
                float4 vt = *(const float4*)(vsrc + 4 * i);
                sVt[(lc + 4 * i + 0) * FSTR + lr] = f2tf(vt.x);
                sVt[(lc + 4 * i + 1) * FSTR + lr] = f2tf(vt.y);
                sVt[(lc + 4 * i + 2) * FSTR + lr] = f2tf(vt.z);
                sVt[(lc + 4 * i + 3) * FSTR + lr] = f2tf(vt.w);
            }
        }
        __syncthreads();

        // ---- S = Q K^T via mma: warp tile 16x64 ----
        float s_frag[8][4];
#pragma unroll
        for (int n = 0; n < 8; n++)
#pragma unroll
            for (int r = 0; r < 4; r++) s_frag[n][r] = 0.f;

#pragma unroll
        for (int ks = 0; ks < 64; ks += 8) {
            uint32_t af[4];
            af[0] = sQ[(rowA + lq) * FSTR + ks + lrm];
            af[1] = sQ[(rowA + lq + 8) * FSTR + ks + lrm];
            af[2] = sQ[(rowA + lq) * FSTR + ks + lrm + 4];
            af[3] = sQ[(rowA + lq + 8) * FSTR + ks + lrm + 4];
#pragma unroll
            for (int n = 0; n < 8; n++) {
                uint32_t bf[2];
                bf[0] = sK[(8 * n + lq) * FSTR + ks + lrm];
                bf[1] = sK[(8 * n + lq) * FSTR + ks + lrm + 4];
                mma_tf32(s_frag[n], af, bf);
            }
        }
#pragma unroll
        for (int n = 0; n < 8; n++)
#pragma unroll
            for (int r = 0; r < 4; r++) s_frag[n][r] *= 0.125f;

        // causal mask on diagonal block (rel col vs rel row; q0 == kb*64 here)
        if (kb == qblk) {
            int r0 = rowA + lq, r1 = rowA + lq + 8;
#pragma unroll
            for (int n = 0; n < 8; n++) {
                int c = 8 * n + 2 * lrm;
                if (c > r0)     s_frag[n][0] = -1e30f;
                if (c + 1 > r0) s_frag[n][1] = -1e30f;
                if (c > r1)     s_frag[n][2] = -1e30f;
                if (c + 1 > r1) s_frag[n][3] = -1e30f;
            }
        }

        // ---- online softmax on fragments (row groups = lrm quads) ----
        {
            float mloc0 = -1e30f, mloc1 = -1e30f;
#pragma unroll
            for (int n = 0; n < 8; n++) {
                mloc0 = fmaxf(mloc0, fmaxf(s_frag[n][0], s_frag[n][1]));
                mloc1 = fmaxf(mloc1, fmaxf(s_frag[n][2], s_frag[n][3]));
            }
            mloc0 = fmaxf(mloc0, __shfl_xor_sync(0xffffffffu, mloc0, 1));
            mloc0 = fmaxf(mloc0, __shfl_xor_sync(0xffffffffu, mloc0, 2));
            mloc1 = fmaxf(mloc1, __shfl_xor_sync(0xffffffffu, mloc1, 1));
            mloc1 = fmaxf(mloc1, __shfl_xor_sync(0xffffffffu, mloc1, 2));
            float mn0 = fmaxf(m0, mloc0), mn1 = fmaxf(m1, mloc1);
            float c0 = __expf(m0 - mn0), c1 = __expf(m1 - mn1);
            float ps0 = 0.f, ps1 = 0.f;
#pragma unroll
            for (int n = 0; n < 8; n++) {
                float p0 = __expf(s_frag[n][0] - mn0);
                float p1 = __expf(s_frag[n][1] - mn0);
                float p2 = __expf(s_frag[n][2] - mn1);
                float p3 = __expf(s_frag[n][3] - mn1);
                s_frag[n][0] = p0; s_frag[n][1] = p1;
                s_frag[n][2] = p2; s_frag[n][3] = p3;
                ps0 += p0 + p1; ps1 += p2 + p3;
            }
            ps0 += __shfl_xor_sync(0xffffffffu, ps0, 1);
            ps0 += __shfl_xor_sync(0xffffffffu, ps0, 2);
            ps1 += __shfl_xor_sync(0xffffffffu, ps1, 1);
            ps1 += __shfl_xor_sync(0xffffffffu, ps1, 2);
            l0 = l0 * c0 + ps0; m0 = mn0;
            l1 = l1 * c1 + ps1; m1 = mn1;
#pragma unroll
            for (int n = 0; n < 8; n++) {
                o_frag[n][0] *= c0; o_frag[n][1] *= c0;
                o_frag[n][2] *= c1; o_frag[n][3] *= c1;
            }
        }

        // ---- write P (tf32) to smem; own-warp rows only -> syncwarp ----
#pragma unroll
        for (int n = 0; n < 8; n++) {
            uint2 p01; p01.x = f2tf(s_frag[n][0]); p01.y = f2tf(s_frag[n][1]);
            *(uint2*)&sP[(rowA + lq) * FSTR + 8 * n + 2 * lrm] = p01;
            uint2 p23; p23.x = f2tf(s_frag[n][2]); p23.y = f2tf(s_frag[n][3]);
            *(uint2*)&sP[(rowA + lq + 8) * FSTR + 8 * n + 2 * lrm] = p23;
        }
        __syncwarp();

        // ---- O += P V via mma (B operand = V^T from sVt) ----
#pragma unroll
        for (int ks = 0; ks < 64; ks += 8) {
            uint32_t af[4];
            af[0] = sP[(rowA + lq) * FSTR + ks + lrm];
            af[1] = sP[(rowA + lq + 8) * FSTR + ks + lrm];
            af[2] = sP[(rowA + lq) * FSTR + ks + lrm + 4];
            af[3] = sP[(rowA + lq + 8) * FSTR + ks + lrm + 4];
#pragma unroll
            for (int n = 0; n < 8; n++) {
                uint32_t bf[2];
                bf[0] = sVt[(8 * n + lq) * FSTR + ks + lrm];
                bf[1] = sVt[(8 * n + lq) * FSTR + ks + lrm + 4];
                mma_tf32(o_frag[n], af, bf);
            }
        }
    }

    // ---- epilogue ----
    float i0 = 1.0f / l0, i1 = 1.0f / l1;
    float* d0 = O + base + (size_t)(q0 + rowA + lq) * DIM;
    float* d1 = O + base + (size_t)(q0 + rowA + lq + 8) * DIM;
#pragma unroll
    for (int n = 0; n < 8; n++) {
        int col = 8 * n + 2 * lrm;
        float2 w0; w0.x = o_frag[n][0] * i0; w0.y = o_frag[n][1] * i0;
        float2 w1; w1.x = o_frag[n][2] * i1; w1.y = o_frag[n][3] * i1;
        *(float2*)&d0[col] = w0;
        *(float2*)&d1[col] = w1;
    }
}

// ---------------------------------------------------------------------------
extern "C" void kernel_launch(void* const* d_in, const int* in_sizes, int n_in,
                              void* d_out, int out_size) {
    const float* x  = (const float*)d_in[0];
    const float* g1 = (const float*)d_in[1];
    const float* b1 = (const float*)d_in[2];
    const float* Wq = (const float*)d_in[3];
    const float* bq = (const float*)d_in[4];
    const float* Wk = (const float*)d_in[5];
    const float* bk = (const float*)d_in[6];
    const float* Wv = (const float*)d_in[7];
    const float* bv = (const float*)d_in[8];
    const float* Wo = (const float*)d_in[9];
    const float* bo = (const float*)d_in[10];
    float* out = (float*)d_out;

    float *h_p, *q_p, *k_p, *v_p, *a_p;
    cudaGetSymbolAddress((void**)&h_p, g_h);
    cudaGetSymbolAddress((void**)&q_p, g_q);
    cudaGetSymbolAddress((void**)&k_p, g_k);
    cudaGetSymbolAddress((void**)&v_p, g_v);
    cudaGetSymbolAddress((void**)&a_p, g_att);

    const int attn_smem = 4 * 64 * FSTR * (int)sizeof(uint32_t);  // 69632 B
    cudaFuncSetAttribute(attn_kernel, cudaFuncAttributeMaxDynamicSharedMemorySize,
                         attn_smem);

    ln_kernel<<<BT, 256>>>(x, g1, b1, h_p);

    dim3 qkv_grid(DIM / 128, BT / 128, 3);
    gemm_qkv<<<qkv_grid, 256>>>(h_p, Wq, bq, q_p, Wk, bk, k_p, Wv, bv, v_p,
                                BT, DIM, DIM);

    attn_kernel<<<dim3(TSEQ / 64, NH, 2), 128, attn_smem>>>(q_p, k_p, v_p, a_p);

    dim3 ggrid(DIM / 128, BT / 128);
    gemm_tf32<<<ggrid, 256>>>(a_p, Wo, bo, out, BT, DIM, DIM);
}

// round 7
// speedup vs baseline: 4.0575x; 1.0216x over previous
#include <cuda_runtime.h>
#include <cstdint>

#define DIM 1024
#define NH 16
#define HD 64
#define TSEQ 2048
#define BT 4096          // B * T
#define GSTR 20          // gemm smem stride (words): conflict-free for tf32 frag loads
#define FSTR 68          // attention smem stride (words): 68 mod 32 = 4 -> frag loads conflict-free

// Scratch (static device arrays; allocation in kernel_launch is forbidden)
__device__ float g_h[BT * DIM];
__device__ float g_q[BT * DIM];
__device__ float g_k[BT * DIM];
__device__ float g_v[BT * DIM];
__device__ float g_att[BT * DIM];

// ---------------------------------------------------------------------------
// LayerNorm: one block per row of x [4096, 1024]
// ---------------------------------------------------------------------------
__global__ void ln_kernel(const float* __restrict__ x,
                          const float* __restrict__ gamma,
                          const float* __restrict__ beta,
                          float* __restrict__ out) {
    int row = blockIdx.x;
    const float* xr = x + (size_t)row * DIM;
    float* orow = out + (size_t)row * DIM;
    int t = threadIdx.x;

    float v[4];
    float sum = 0.f, sq = 0.f;
#pragma unroll
    for (int i = 0; i < 4; i++) {
        float val = xr[t + i * 256];
        v[i] = val;
        sum += val;
        sq += val * val;
    }
#pragma unroll
    for (int o = 16; o > 0; o >>= 1) {
        sum += __shfl_xor_sync(0xffffffffu, sum, o);
        sq  += __shfl_xor_sync(0xffffffffu, sq, o);
    }
    __shared__ float s1[8], s2[8];
    if ((t & 31) == 0) { s1[t >> 5] = sum; s2[t >> 5] = sq; }
    __syncthreads();
    float tot = 0.f, totq = 0.f;
#pragma unroll
    for (int i = 0; i < 8; i++) { tot += s1[i]; totq += s2[i]; }
    float mu   = tot * (1.0f / DIM);
    float var  = totq * (1.0f / DIM) - mu * mu;
    float rstd = rsqrtf(var + 1e-5f);
#pragma unroll
    for (int i = 0; i < 4; i++) {
        int c = t + i * 256;
        orow[c] = (v[i] - mu) * rstd * gamma[c] + beta[c];
    }
}

// ---------------------------------------------------------------------------
// tf32 helpers
// ---------------------------------------------------------------------------
__device__ __forceinline__ uint32_t f2tf(float x) {
    uint32_t y;
    asm("cvt.rna.tf32.f32 %0, %1;" : "=r"(y) : "f"(x));
    return y;
}

__device__ __forceinline__ void mma_tf32(float* c, const uint32_t* a,
                                         const uint32_t* b) {
    asm volatile(
        "mma.sync.aligned.m16n8k8.row.col.f32.tf32.tf32.f32 "
        "{%0,%1,%2,%3}, {%4,%5,%6,%7}, {%8,%9}, {%0,%1,%2,%3};\n"
        : "+f"(c[0]), "+f"(c[1]), "+f"(c[2]), "+f"(c[3])
        : "r"(a[0]), "r"(a[1]), "r"(a[2]), "r"(a[3]), "r"(b[0]), "r"(b[1]));
}

// ---------------------------------------------------------------------------
// tf32 GEMM NT, 2-stage smem double buffer:
// C[m][n] = sum_k A[m][k]*B[n][k] + bias[n]
// 128x128 tile, BK=16, 256 threads = 8 warps (2 m x 4 n), warp tile 64x32.
// Per iteration: LDG(next) -> MMA(cur) -> STS(next) -> one sync.
// ---------------------------------------------------------------------------
__device__ __forceinline__ void gemm_tf32_body(const float* __restrict__ A,
                                               const float* __restrict__ B,
                                               const float* __restrict__ bias,
                                               float* __restrict__ C,
                                               int M, int N, int K) {
    __shared__ uint32_t As[2][128 * GSTR];
    __shared__ uint32_t Bs[2][128 * GSTR];

    int tid = threadIdx.x;
    int bm = blockIdx.y * 128;
    int bn = blockIdx.x * 128;
    int w = tid >> 5, lane = tid & 31;
    int wm = (w & 1) * 64;        // warp m offset
    int wn = (w >> 1) * 32;       // warp n offset
    int lq = lane >> 2;           // lane/4
    int lrm = lane & 3;           // lane%4
    int lr = tid >> 2;            // load row 0..63
    int lc = (tid & 3) << 2;      // load k offset 0,4,8,12

    const float* Ap = A + (size_t)(bm + lr) * K + lc;
    const float* Bp = B + (size_t)(bn + lr) * K + lc;

    float acc[4][4][4];
#pragma unroll
    for (int mi = 0; mi < 4; mi++)
#pragma unroll
        for (int ni = 0; ni < 4; ni++)
#pragma unroll
            for (int r = 0; r < 4; r++) acc[mi][ni][r] = 0.f;

    // Prologue: load + store stage 0
    {
        float4 a0 = *(const float4*)(Ap);
        float4 a1 = *(const float4*)(Ap + (size_t)64 * K);
        float4 b0 = *(const float4*)(Bp);
        float4 b1 = *(const float4*)(Bp + (size_t)64 * K);
        uint4 u;
        u.x = f2tf(a0.x); u.y = f2tf(a0.y); u.z = f2tf(a0.z); u.w = f2tf(a0.w);
        *(uint4*)&As[0][lr * GSTR + lc] = u;
        u.x = f2tf(a1.x); u.y = f2tf(a1.y); u.z = f2tf(a1.z); u.w = f2tf(a1.w);
        *(uint4*)&As[0][(lr + 64) * GSTR + lc] = u;
        u.x = f2tf(b0.x); u.y = f2tf(b0.y); u.z = f2tf(b0.z); u.w = f2tf(b0.w);
        *(uint4*)&Bs[0][lr * GSTR + lc] = u;
        u.x = f2tf(b1.x); u.y = f2tf(b1.y); u.z = f2tf(b1.z); u.w = f2tf(b1.w);
        *(uint4*)&Bs[0][(lr + 64) * GSTR + lc] = u;
    }
    __syncthreads();

    int stage = 0;
    for (int k0 = 0; k0 < K; k0 += 16) {
        int nxt = stage ^ 1;
        bool has_next = (k0 + 16) < K;

        // Issue next tile's global loads before the MMA section (latency hidden)
        float4 a0, a1, b0, b1;
        if (has_next) {
            a0 = *(const float4*)(Ap + k0 + 16);
            a1 = *(const float4*)(Ap + (size_t)64 * K + k0 + 16);
            b0 = *(const float4*)(Bp + k0 + 16);
            b1 = *(const float4*)(Bp + (size_t)64 * K + k0 + 16);
        }

        // MMA on current stage
#pragma unroll
        for (int ks = 0; ks < 16; ks += 8) {
            uint32_t af[4][4], bf[4][2];
#pragma unroll
            for (int mi = 0; mi < 4; mi++) {
                int rowA = wm + mi * 16;
                af[mi][0] = As[stage][(rowA + lq) * GSTR + ks + lrm];
                af[mi][1] = As[stage][(rowA + lq + 8) * GSTR + ks + lrm];
                af[mi][2] = As[stage][(rowA + lq) * GSTR + ks + lrm + 4];
                af[mi][3] = As[stage][(rowA + lq + 8) * GSTR + ks + lrm + 4];
            }
#pragma unroll
            for (int ni = 0; ni < 4; ni++) {
                int rowB = wn + ni * 8;
                bf[ni][0] = Bs[stage][(rowB + lq) * GSTR + ks + lrm];
                bf[ni][1] = Bs[stage][(rowB + lq) * GSTR + ks + lrm + 4];
            }
#pragma unroll
            for (int mi = 0; mi < 4; mi++)
#pragma unroll
                for (int ni = 0; ni < 4; ni++)
                    mma_tf32(acc[mi][ni], af[mi], bf[ni]);
        }

        // Store next tile into the other stage (no race: distinct buffer)
        if (has_next) {
            uint4 u;
            u.x = f2tf(a0.x); u.y = f2tf(a0.y); u.z = f2tf(a0.z); u.w = f2tf(a0.w);
            *(uint4*)&As[nxt][lr * GSTR + lc] = u;
            u.x = f2tf(a1.x); u.y = f2tf(a1.y); u.z = f2tf(a1.z); u.w = f2tf(a1.w);
            *(uint4*)&As[nxt][(lr + 64) * GSTR + lc] = u;
            u.x = f2tf(b0.x); u.y = f2tf(b0.y); u.z = f2tf(b0.z); u.w = f2tf(b0.w);
            *(uint4*)&Bs[nxt][lr * GSTR + lc] = u;
            u.x = f2tf(b1.x); u.y = f2tf(b1.y); u.z = f2tf(b1.z); u.w = f2tf(b1.w);
            *(uint4*)&Bs[nxt][(lr + 64) * GSTR + lc] = u;
            __syncthreads();
        }
        stage = nxt;
    }

#pragma unroll
    for (int mi = 0; mi < 4; mi++) {
#pragma unroll
        for (int ni = 0; ni < 4; ni++) {
            int row0 = bm + wm + mi * 16 + lq;
            int col  = bn + wn + ni * 8 + lrm * 2;
            float2 bb = *(const float2*)&bias[col];
            float2 o0, o1;
            o0.x = acc[mi][ni][0] + bb.x;
            o0.y = acc[mi][ni][1] + bb.y;
            o1.x = acc[mi][ni][2] + bb.x;
            o1.y = acc[mi][ni][3] + bb.y;
            *(float2*)&C[(size_t)row0 * N + col] = o0;
            *(float2*)&C[(size_t)(row0 + 8) * N + col] = o1;
        }
    }
}

// Single GEMM (O-projection)
__global__ __launch_bounds__(256) void gemm_tf32(const float* __restrict__ A,
                                                 const float* __restrict__ B,
                                                 const float* __restrict__ bias,
                                                 float* __restrict__ C,
                                                 int M, int N, int K) {
    gemm_tf32_body(A, B, bias, C, M, N, K);
}

// Fused QKV GEMM: blockIdx.z selects weight/bias/output (args, capture-safe)
__global__ __launch_bounds__(256) void gemm_qkv(const float* __restrict__ A,
                                                const float* __restrict__ Wq,
                                                const float* __restrict__ bq,
                                                float* __restrict__ Oq,
                                                const float* __restrict__ Wk,
                                                const float* __restrict__ bk,
                                                float* __restrict__ Ok,
                                                const float* __restrict__ Wv,
                                                const float* __restrict__ bv,
                                                float* __restrict__ Ov,
                                                int M, int N, int K) {
    int z = blockIdx.z;
    const float* W = (z == 0) ? Wq : (z == 1) ? Wk : Wv;
    const float* b = (z == 0) ? bq : (z == 1) ? bk : bv;
    float* O       = (z == 0) ? Oq : (z == 1) ? Ok : Ov;
    gemm_tf32_body(A, W, b, O, M, N, K);
}

// ---------------------------------------------------------------------------
// Tensor-core causal flash attention (tf32 mma, fp32 accum/softmax).
// Grid: (T/64, NH, B). Block: 128 threads = 4 warps; warp w owns q rows
// [16w, 16w+16). 64x64 tiles. S and PV via mma.sync.m16n8k8.
// smem: sQ, sK, sVt (V transposed: [d][key]), sP — all tf32, stride FSTR=68.
// ---------------------------------------------------------------------------
__global__ __launch_bounds__(128) void attn_kernel(const float* __restrict__ Q,
                                                   const float* __restrict__ K,
                                                   const float* __restrict__ V,
                                                   float* __restrict__ O) {
    extern __shared__ uint32_t sm[];
    uint32_t* sQ  = sm;                 // 64*FSTR
    uint32_t* sK  = sQ + 64 * FSTR;
    uint32_t* sVt = sK + 64 * FSTR;     // sVt[d*FSTR + key]
    uint32_t* sP  = sVt + 64 * FSTR;

    int tid = threadIdx.x;
    int w = tid >> 5, lane = tid & 31;
    int lq = lane >> 2, lrm = lane & 3;
    int rowA = w * 16;
    int qblk = blockIdx.x;
    int h = blockIdx.y;
    int b = blockIdx.z;
    int q0 = qblk * 64;
    size_t base = ((size_t)b * TSEQ) * DIM + h * HD;

    int lr = tid >> 1;            // load row 0..63
    int lc = (tid & 1) * 32;      // load col offset 0/32

    // Load Q tile once (as tf32)
    {
        const float* src = Q + base + (size_t)(q0 + lr) * DIM + lc;
        uint32_t* dst = sQ + lr * FSTR + lc;
#pragma unroll
        for (int i = 0; i < 8; i++) {
            float4 t4 = *(const float4*)(src + 4 * i);
            dst[4 * i + 0] = f2tf(t4.x); dst[4 * i + 1] = f2tf(t4.y);
            dst[4 * i + 2] = f2tf(t4.z); dst[4 * i + 3] = f2tf(t4.w);
        }
    }

    float o_frag[8][4];
#pragma unroll
    for (int n = 0; n < 8; n++)
#pragma unroll
        for (int r = 0; r < 4; r++) o_frag[n][r] = 0.f;
    float m0 = -1e30f, m1 = -1e30f, l0 = 0.f, l1 = 0.f;

    for (int kb = 0; kb <= qblk; kb++) {
        __syncthreads();  // all warps done with prior sK/sVt before refill
        {
            const float* ksrc = K + base + (size_t)(kb * 64 + lr) * DIM + lc;
            const float* vsrc = V + base + (size_t)(kb * 64 + lr) * DIM + lc;
            uint32_t* kd = sK + lr * FSTR + lc;
#pragma unroll
            for (int i = 0; i < 8; i++) {
                float4 kt = *(const float4*)(ksrc + 4 * i);
                kd[4 * i + 0] = f2tf(kt.x); kd[4 * i + 1] = f2tf(kt.y);
                kd[4 * i + 2] = f2tf(kt.z); kd[4 * i + 3] = f2tf(kt.w);
                float4 vt = *(const float4*)(vsrc + 4 * i);
                sVt[(lc + 4 * i + 0) * FSTR + lr] = f2tf(vt.x);
                sVt[(lc + 4 * i + 1) * FSTR + lr] = f2tf(vt.y);
                sVt[(lc + 4 * i + 2) * FSTR + lr] = f2tf(vt.z);
                sVt[(lc + 4 * i + 3) * FSTR + lr] = f2tf(vt.w);
            }
        }
        __syncthreads();

        // ---- S = Q K^T via mma: warp tile 16x64 ----
        float s_frag[8][4];
#pragma unroll
        for (int n = 0; n < 8; n++)
#pragma unroll
            for (int r = 0; r < 4; r++) s_frag[n][r] = 0.f;

#pragma unroll
        for (int ks = 0; ks < 64; ks += 8) {
            uint32_t af[4];
            af[0] = sQ[(rowA + lq) * FSTR + ks + lrm];
            af[1] = sQ[(rowA + lq + 8) * FSTR + ks + lrm];
            af[2] = sQ[(rowA + lq) * FSTR + ks + lrm + 4];
            af[3] = sQ[(rowA + lq + 8) * FSTR + ks + lrm + 4];
#pragma unroll
            for (int n = 0; n < 8; n++) {
                uint32_t bf[2];
                bf[0] = sK[(8 * n + lq) * FSTR + ks + lrm];
                bf[1] = sK[(8 * n + lq) * FSTR + ks + lrm + 4];
                mma_tf32(s_frag[n], af, bf);
            }
        }
#pragma unroll
        for (int n = 0; n < 8; n++)
#pragma unroll
            for (int r = 0; r < 4; r++) s_frag[n][r] *= 0.125f;

        // causal mask on diagonal block (rel col vs rel row; q0 == kb*64 here)
        if (kb == qblk) {
            int r0 = rowA + lq, r1 = rowA + lq + 8;
#pragma unroll
            for (int n = 0; n < 8; n++) {
                int c = 8 * n + 2 * lrm;
                if (c > r0)     s_frag[n][0] = -1e30f;
                if (c + 1 > r0) s_frag[n][1] = -1e30f;
                if (c > r1)     s_frag[n][2] = -1e30f;
                if (c + 1 > r1) s_frag[n][3] = -1e30f;
            }
        }

        // ---- online softmax on fragments (row groups = lrm quads) ----
        {
            float mloc0 = -1e30f, mloc1 = -1e30f;
#pragma unroll
            for (int n = 0; n < 8; n++) {
                mloc0 = fmaxf(mloc0, fmaxf(s_frag[n][0], s_frag[n][1]));
                mloc1 = fmaxf(mloc1, fmaxf(s_frag[n][2], s_frag[n][3]));
            }
            mloc0 = fmaxf(mloc0, __shfl_xor_sync(0xffffffffu, mloc0, 1));
            mloc0 = fmaxf(mloc0, __shfl_xor_sync(0xffffffffu, mloc0, 2));
            mloc1 = fmaxf(mloc1, __shfl_xor_sync(0xffffffffu, mloc1, 1));
            mloc1 = fmaxf(mloc1, __shfl_xor_sync(0xffffffffu, mloc1, 2));
            float mn0 = fmaxf(m0, mloc0), mn1 = fmaxf(m1, mloc1);
            float c0 = __expf(m0 - mn0), c1 = __expf(m1 - mn1);
            float ps0 = 0.f, ps1 = 0.f;
#pragma unroll
            for (int n = 0; n < 8; n++) {
                float p0 = __expf(s_frag[n][0] - mn0);
                float p1 = __expf(s_frag[n][1] - mn0);
                float p2 = __expf(s_frag[n][2] - mn1);
                float p3 = __expf(s_frag[n][3] - mn1);
                s_frag[n][0] = p0; s_frag[n][1] = p1;
                s_frag[n][2] = p2; s_frag[n][3] = p3;
                ps0 += p0 + p1; ps1 += p2 + p3;
            }
            ps0 += __shfl_xor_sync(0xffffffffu, ps0, 1);
            ps0 += __shfl_xor_sync(0xffffffffu, ps0, 2);
            ps1 += __shfl_xor_sync(0xffffffffu, ps1, 1);
            ps1 += __shfl_xor_sync(0xffffffffu, ps1, 2);
            l0 = l0 * c0 + ps0; m0 = mn0;
            l1 = l1 * c1 + ps1; m1 = mn1;
#pragma unroll
            for (int n = 0; n < 8; n++) {
                o_frag[n][0] *= c0; o_frag[n][1] *= c0;
                o_frag[n][2] *= c1; o_frag[n][3] *= c1;
            }
        }

        // ---- write P (tf32) to smem; own-warp rows only -> syncwarp ----
#pragma unroll
        for (int n = 0; n < 8; n++) {
            uint2 p01; p01.x = f2tf(s_frag[n][0]); p01.y = f2tf(s_frag[n][1]);
            *(uint2*)&sP[(rowA + lq) * FSTR + 8 * n + 2 * lrm] = p01;
            uint2 p23; p23.x = f2tf(s_frag[n][2]); p23.y = f2tf(s_frag[n][3]);
            *(uint2*)&sP[(rowA + lq + 8) * FSTR + 8 * n + 2 * lrm] = p23;
        }
        __syncwarp();

        // ---- O += P V via mma (B operand = V^T from sVt) ----
#pragma unroll
        for (int ks = 0; ks < 64; ks += 8) {
            uint32_t af[4];
            af[0] = sP[(rowA + lq) * FSTR + ks + lrm];
            af[1] = sP[(rowA + lq + 8) * FSTR + ks + lrm];
            af[2] = sP[(rowA + lq) * FSTR + ks + lrm + 4];
            af[3] = sP[(rowA + lq + 8) * FSTR + ks + lrm + 4];
#pragma unroll
            for (int n = 0; n < 8; n++) {
                uint32_t bf[2];
                bf[0] = sVt[(8 * n + lq) * FSTR + ks + lrm];
                bf[1] = sVt[(8 * n + lq) * FSTR + ks + lrm + 4];
                mma_tf32(o_frag[n], af, bf);
            }
        }
    }

    // ---- epilogue ----
    float i0 = 1.0f / l0, i1 = 1.0f / l1;
    float* d0 = O + base + (size_t)(q0 + rowA + lq) * DIM;
    float* d1 = O + base + (size_t)(q0 + rowA + lq + 8) * DIM;
#pragma unroll
    for (int n = 0; n < 8; n++) {
        int col = 8 * n + 2 * lrm;
        float2 w0; w0.x = o_frag[n][0] * i0; w0.y = o_frag[n][1] * i0;
        float2 w1; w1.x = o_frag[n][2] * i1; w1.y = o_frag[n][3] * i1;
        *(float2*)&d0[col] = w0;
        *(float2*)&d1[col] = w1;
    }
}

// ---------------------------------------------------------------------------
extern "C" void kernel_launch(void* const* d_in, const int* in_sizes, int n_in,
                              void* d_out, int out_size) {
    const float* x  = (const float*)d_in[0];
    const float* g1 = (const float*)d_in[1];
    const float* b1 = (const float*)d_in[2];
    const float* Wq = (const float*)d_in[3];
    const float* bq = (const float*)d_in[4];
    const float* Wk = (const float*)d_in[5];
    const float* bk = (const float*)d_in[6];
    const float* Wv = (const float*)d_in[7];
    const float* bv = (const float*)d_in[8];
    const float* Wo = (const float*)d_in[9];
    const float* bo = (const float*)d_in[10];
    float* out = (float*)d_out;

    float *h_p, *q_p, *k_p, *v_p, *a_p;
    cudaGetSymbolAddress((void**)&h_p, g_h);
    cudaGetSymbolAddress((void**)&q_p, g_q);
    cudaGetSymbolAddress((void**)&k_p, g_k);
    cudaGetSymbolAddress((void**)&v_p, g_v);
    cudaGetSymbolAddress((void**)&a_p, g_att);

    const int attn_smem = 4 * 64 * FSTR * (int)sizeof(uint32_t);  // 69632 B
    cudaFuncSetAttribute(attn_kernel, cudaFuncAttributeMaxDynamicSharedMemorySize,
                         attn_smem);

    ln_kernel<<<BT, 256>>>(x, g1, b1, h_p);

    dim3 qkv_grid(DIM / 128, BT / 128, 3);
    gemm_qkv<<<qkv_grid, 256>>>(h_p, Wq, bq, q_p, Wk, bk, k_p, Wv, bv, v_p,
                                BT, DIM, DIM);

    attn_kernel<<<dim3(TSEQ / 64, NH, 2), 128, attn_smem>>>(q_p, k_p, v_p, a_p);

    dim3 ggrid(DIM / 128, BT / 128);
    gemm_tf32<<<ggrid, 256>>>(a_p, Wo, bo, out, BT, DIM, DIM);
}

// round 8
// speedup vs baseline: 4.4736x; 1.1025x over previous
#include <cuda_runtime.h>
#include <cstdint>

#define DIM 1024
#define NH 16
#define HD 64
#define TSEQ 2048
#define BT 4096          // B * T
#define GSTR 20          // gemm smem stride (words): conflict-free for tf32 frag loads
#define FSTR 68          // attention smem stride (words): 68 mod 32 = 4 -> frag loads conflict-free
#define QT 128           // attention query-tile rows

// Scratch (static device arrays; allocation in kernel_launch is forbidden)
__device__ float g_h[BT * DIM];
__device__ float g_q[BT * DIM];
__device__ float g_k[BT * DIM];
__device__ float g_v[BT * DIM];
__device__ float g_att[BT * DIM];

// ---------------------------------------------------------------------------
// LayerNorm: one block per row of x [4096, 1024]
// ---------------------------------------------------------------------------
__global__ void ln_kernel(const float* __restrict__ x,
                          const float* __restrict__ gamma,
                          const float* __restrict__ beta,
                          float* __restrict__ out) {
    int row = blockIdx.x;
    const float* xr = x + (size_t)row * DIM;
    float* orow = out + (size_t)row * DIM;
    int t = threadIdx.x;

    float v[4];
    float sum = 0.f, sq = 0.f;
#pragma unroll
    for (int i = 0; i < 4; i++) {
        float val = xr[t + i * 256];
        v[i] = val;
        sum += val;
        sq += val * val;
    }
#pragma unroll
    for (int o = 16; o > 0; o >>= 1) {
        sum += __shfl_xor_sync(0xffffffffu, sum, o);
        sq  += __shfl_xor_sync(0xffffffffu, sq, o);
    }
    __shared__ float s1[8], s2[8];
    if ((t & 31) == 0) { s1[t >> 5] = sum; s2[t >> 5] = sq; }
    __syncthreads();
    float tot = 0.f, totq = 0.f;
#pragma unroll
    for (int i = 0; i < 8; i++) { tot += s1[i]; totq += s2[i]; }
    float mu   = tot * (1.0f / DIM);
    float var  = totq * (1.0f / DIM) - mu * mu;
    float rstd = rsqrtf(var + 1e-5f);
#pragma unroll
    for (int i = 0; i < 4; i++) {
        int c = t + i * 256;
        orow[c] = (v[i] - mu) * rstd * gamma[c] + beta[c];
    }
}

// ---------------------------------------------------------------------------
// tf32 helpers
// ---------------------------------------------------------------------------
__device__ __forceinline__ uint32_t f2tf(float x) {
    uint32_t y;
    asm("cvt.rna.tf32.f32 %0, %1;" : "=r"(y) : "f"(x));
    return y;
}

__device__ __forceinline__ void mma_tf32(float* c, const uint32_t* a,
                                         const uint32_t* b) {
    asm volatile(
        "mma.sync.aligned.m16n8k8.row.col.f32.tf32.tf32.f32 "
        "{%0,%1,%2,%3}, {%4,%5,%6,%7}, {%8,%9}, {%0,%1,%2,%3};\n"
        : "+f"(c[0]), "+f"(c[1]), "+f"(c[2]), "+f"(c[3])
        : "r"(a[0]), "r"(a[1]), "r"(a[2]), "r"(a[3]), "r"(b[0]), "r"(b[1]));
}

// ---------------------------------------------------------------------------
// tf32 GEMM NT, 2-stage smem double buffer (frozen from R6).
// ---------------------------------------------------------------------------
__device__ __forceinline__ void gemm_tf32_body(const float* __restrict__ A,
                                               const float* __restrict__ B,
                                               const float* __restrict__ bias,
                                               float* __restrict__ C,
                                               int M, int N, int K) {
    __shared__ uint32_t As[2][128 * GSTR];
    __shared__ uint32_t Bs[2][128 * GSTR];

    int tid = threadIdx.x;
    int bm = blockIdx.y * 128;
    int bn = blockIdx.x * 128;
    int w = tid >> 5, lane = tid & 31;
    int wm = (w & 1) * 64;
    int wn = (w >> 1) * 32;
    int lq = lane >> 2;
    int lrm = lane & 3;
    int lr = tid >> 2;
    int lc = (tid & 3) << 2;

    const float* Ap = A + (size_t)(bm + lr) * K + lc;
    const float* Bp = B + (size_t)(bn + lr) * K + lc;

    float acc[4][4][4];
#pragma unroll
    for (int mi = 0; mi < 4; mi++)
#pragma unroll
        for (int ni = 0; ni < 4; ni++)
#pragma unroll
            for (int r = 0; r < 4; r++) acc[mi][ni][r] = 0.f;

    {
        float4 a0 = *(const float4*)(Ap);
        float4 a1 = *(const float4*)(Ap + (size_t)64 * K);
        float4 b0 = *(const float4*)(Bp);
        float4 b1 = *(const float4*)(Bp + (size_t)64 * K);
        uint4 u;
        u.x = f2tf(a0.x); u.y = f2tf(a0.y); u.z = f2tf(a0.z); u.w = f2tf(a0.w);
        *(uint4*)&As[0][lr * GSTR + lc] = u;
        u.x = f2tf(a1.x); u.y = f2tf(a1.y); u.z = f2tf(a1.z); u.w = f2tf(a1.w);
        *(uint4*)&As[0][(lr + 64) * GSTR + lc] = u;
        u.x = f2tf(b0.x); u.y = f2tf(b0.y); u.z = f2tf(b0.z); u.w = f2tf(b0.w);
        *(uint4*)&Bs[0][lr * GSTR + lc] = u;
        u.x = f2tf(b1.x); u.y = f2tf(b1.y); u.z = f2tf(b1.z); u.w = f2tf(b1.w);
        *(uint4*)&Bs[0][(lr + 64) * GSTR + lc] = u;
    }
    __syncthreads();

    int stage = 0;
    for (int k0 = 0; k0 < K; k0 += 16) {
        int nxt = stage ^ 1;
        bool has_next = (k0 + 16) < K;

        float4 a0, a1, b0, b1;
        if (has_next) {
            a0 = *(const float4*)(Ap + k0 + 16);
            a1 = *(const float4*)(Ap + (size_t)64 * K + k0 + 16);
            b0 = *(const float4*)(Bp + k0 + 16);
            b1 = *(const float4*)(Bp + (size_t)64 * K + k0 + 16);
        }

#pragma unroll
        for (int ks = 0; ks < 16; ks += 8) {
            uint32_t af[4][4], bf[4][2];
#pragma unroll
            for (int mi = 0; mi < 4; mi++) {
                int rowA = wm + mi * 16;
                af[mi][0] = As[stage][(rowA + lq) * GSTR + ks + lrm];
                af[mi][1] = As[stage][(rowA + lq + 8) * GSTR + ks + lrm];
                af[mi][2] = As[stage][(rowA + lq) * GSTR + ks + lrm + 4];
                af[mi][3] = As[stage][(rowA + lq + 8) * GSTR + ks + lrm + 4];
            }
#pragma unroll
            for (int ni = 0; ni < 4; ni++) {
                int rowB = wn + ni * 8;
                bf[ni][0] = Bs[stage][(rowB + lq) * GSTR + ks + lrm];
                bf[ni][1] = Bs[stage][(rowB + lq) * GSTR + ks + lrm + 4];
            }
#pragma unroll
            for (int mi = 0; mi < 4; mi++)
#pragma unroll
                for (int ni = 0; ni < 4; ni++)
                    mma_tf32(acc[mi][ni], af[mi], bf[ni]);
        }

        if (has_next) {
            uint4 u;
            u.x = f2tf(a0.x); u.y = f2tf(a0.y); u.z = f2tf(a0.z); u.w = f2tf(a0.w);
            *(uint4*)&As[nxt][lr * GSTR + lc] = u;
            u.x = f2tf(a1.x); u.y = f2tf(a1.y); u.z = f2tf(a1.z); u.w = f2tf(a1.w);
            *(uint4*)&As[nxt][(lr + 64) * GSTR + lc] = u;
            u.x = f2tf(b0.x); u.y = f2tf(b0.y); u.z = f2tf(b0.z); u.w = f2tf(b0.w);
            *(uint4*)&Bs[nxt][lr * GSTR + lc] = u;
            u.x = f2tf(b1.x); u.y = f2tf(b1.y); u.z = f2tf(b1.z); u.w = f2tf(b1.w);
            *(uint4*)&Bs[nxt][(lr + 64) * GSTR + lc] = u;
            __syncthreads();
        }
        stage = nxt;
    }

#pragma unroll
    for (int mi = 0; mi < 4; mi++) {
#pragma unroll
        for (int ni = 0; ni < 4; ni++) {
            int row0 = bm + wm + mi * 16 + lq;
            int col  = bn + wn + ni * 8 + lrm * 2;
            float2 bb = *(const float2*)&bias[col];
            float2 o0, o1;
            o0.x = acc[mi][ni][0] + bb.x;
            o0.y = acc[mi][ni][1] + bb.y;
            o1.x = acc[mi][ni][2] + bb.x;
            o1.y = acc[mi][ni][3] + bb.y;
            *(float2*)&C[(size_t)row0 * N + col] = o0;
            *(float2*)&C[(size_t)(row0 + 8) * N + col] = o1;
        }
    }
}

__global__ __launch_bounds__(256) void gemm_tf32(const float* __restrict__ A,
                                                 const float* __restrict__ B,
                                                 const float* __restrict__ bias,
                                                 float* __restrict__ C,
                                                 int M, int N, int K) {
    gemm_tf32_body(A, B, bias, C, M, N, K);
}

__global__ __launch_bounds__(256) void gemm_qkv(const float* __restrict__ A,
                                                const float* __restrict__ Wq,
                                                const float* __restrict__ bq,
                                                float* __restrict__ Oq,
                                                const float* __restrict__ Wk,
                                                const float* __restrict__ bk,
                                                float* __restrict__ Ok,
                                                const float* __restrict__ Wv,
                                                const float* __restrict__ bv,
                                                float* __restrict__ Ov,
                                                int M, int N, int K) {
    int z = blockIdx.z;
    const float* W = (z == 0) ? Wq : (z == 1) ? Wk : Wv;
    const float* b = (z == 0) ? bq : (z == 1) ? bk : bv;
    float* O       = (z == 0) ? Oq : (z == 1) ? Ok : Ov;
    gemm_tf32_body(A, W, b, O, M, N, K);
}

// ---------------------------------------------------------------------------
// Tensor-core causal flash attention, 128-row Q tile.
// Grid: (T/128, NH, B). Block: 256 threads = 8 warps; warp w owns q rows
// [16w, 16w+16). K tiles of 64. S and PV via mma.sync.m16n8k8 (tf32).
// smem: sQ[128], sK[64], sVt[64 d-major], sP[128] — stride FSTR=68 words.
// Loader mappings (conflict-aware):
//   Q: row = tid>>1, cols (tid&1)*32..+32      (8 float4)
//   K: row = tid&63, cols (tid>>6)*16..+16     (4 float4, row-major store)
//   V: row = tid&63, cols (tid>>6)*16..+16     (4 float4, transposed store;
//      lanes span 32 consecutive rows -> 32 distinct banks, conflict-free)
// ---------------------------------------------------------------------------
__global__ __launch_bounds__(256) void attn_kernel(const float* __restrict__ Q,
                                                   const float* __restrict__ K,
                                                   const float* __restrict__ V,
                                                   float* __restrict__ O) {
    extern __shared__ uint32_t sm[];
    uint32_t* sQ  = sm;                   // QT*FSTR
    uint32_t* sK  = sQ + QT * FSTR;       // 64*FSTR
    uint32_t* sVt = sK + 64 * FSTR;       // 64*FSTR  (sVt[d*FSTR + key])
    uint32_t* sP  = sVt + 64 * FSTR;      // QT*FSTR

    int tid = threadIdx.x;
    int w = tid >> 5, lane = tid & 31;
    int lq = lane >> 2, lrm = lane & 3;
    int rowA = w * 16;
    int qblk = blockIdx.x;
    int h = blockIdx.y;
    int b = blockIdx.z;
    int q0 = qblk * QT;
    size_t base = ((size_t)b * TSEQ) * DIM + h * HD;

    // Q loader mapping
    int qlr = tid >> 1;             // 0..127
    int qlc = (tid & 1) * 32;       // 0/32
    // K/V loader mapping
    int klr = tid & 63;             // 0..63
    int klc = (tid >> 6) * 16;      // 0,16,32,48

    // Load Q tile once (as tf32)
    {
        const float* src = Q + base + (size_t)(q0 + qlr) * DIM + qlc;
        uint32_t* dst = sQ + qlr * FSTR + qlc;
#pragma unroll
        for (int i = 0; i < 8; i++) {
            float4 t4 = *(const float4*)(src + 4 * i);
            dst[4 * i + 0] = f2tf(t4.x); dst[4 * i + 1] = f2tf(t4.y);
            dst[4 * i + 2] = f2tf(t4.z); dst[4 * i + 3] = f2tf(t4.w);
        }
    }

    float o_frag[8][4];
#pragma unroll
    for (int n = 0; n < 8; n++)
#pragma unroll
        for (int r = 0; r < 4; r++) o_frag[n][r] = 0.f;
    float m0 = -1e30f, m1 = -1e30f, l0 = 0.f, l1 = 0.f;

    int kb_max = 2 * qblk + 1;   // K tiles cover [0, q0+QT)
    for (int kb = 0; kb <= kb_max; kb++) {
        __syncthreads();  // all warps done with prior sK/sVt before refill
        {
            const float* ksrc = K + base + (size_t)(kb * 64 + klr) * DIM + klc;
            const float* vsrc = V + base + (size_t)(kb * 64 + klr) * DIM + klc;
            uint32_t* kd = sK + klr * FSTR + klc;
#pragma unroll
            for (int i = 0; i < 4; i++) {
                float4 kt = *(const float4*)(ksrc + 4 * i);
                uint4 u;
                u.x = f2tf(kt.x); u.y = f2tf(kt.y);
                u.z = f2tf(kt.z); u.w = f2tf(kt.w);
                *(uint4*)&kd[4 * i] = u;
                float4 vt = *(const float4*)(vsrc + 4 * i);
                sVt[(klc + 4 * i + 0) * FSTR + klr] = f2tf(vt.x);
                sVt[(klc + 4 * i + 1) * FSTR + klr] = f2tf(vt.y);
                sVt[(klc + 4 * i + 2) * FSTR + klr] = f2tf(vt.z);
                sVt[(klc + 4 * i + 3) * FSTR + klr] = f2tf(vt.w);
            }
        }
        __syncthreads();

        // Fully-masked tile for this warp? (tile min col > warp max row)
        // warp rows: q0+rowA .. q0+rowA+15 ; tile cols: kb*64 .. kb*64+63
        if (kb * 64 > q0 + rowA + 15) continue;   // warp-uniform

        // ---- S = Q K^T via mma: warp tile 16x64 ----
        float s_frag[8][4];
#pragma unroll
        for (int n = 0; n < 8; n++)
#pragma unroll
            for (int r = 0; r < 4; r++) s_frag[n][r] = 0.f;

#pragma unroll
        for (int ks = 0; ks < 64; ks += 8) {
            uint32_t af[4];
            af[0] = sQ[(rowA + lq) * FSTR + ks + lrm];
            af[1] = sQ[(rowA + lq + 8) * FSTR + ks + lrm];
            af[2] = sQ[(rowA + lq) * FSTR + ks + lrm + 4];
            af[3] = sQ[(rowA + lq + 8) * FSTR + ks + lrm + 4];
#pragma unroll
            for (int n = 0; n < 8; n++) {
                uint32_t bf[2];
                bf[0] = sK[(8 * n + lq) * FSTR + ks + lrm];
                bf[1] = sK[(8 * n + lq) * FSTR + ks + lrm + 4];
                mma_tf32(s_frag[n], af, bf);
            }
        }
#pragma unroll
        for (int n = 0; n < 8; n++)
#pragma unroll
            for (int r = 0; r < 4; r++) s_frag[n][r] *= 0.125f;

        // causal mask (global indices) on partially masked tiles
        if (kb * 64 + 63 > q0 + rowA) {
            int r0 = q0 + rowA + lq, r1 = q0 + rowA + lq + 8;
            int cbase = kb * 64;
#pragma unroll
            for (int n = 0; n < 8; n++) {
                int c = cbase + 8 * n + 2 * lrm;
                if (c > r0)     s_frag[n][0] = -1e30f;
                if (c + 1 > r0) s_frag[n][1] = -1e30f;
                if (c > r1)     s_frag[n][2] = -1e30f;
                if (c + 1 > r1) s_frag[n][3] = -1e30f;
            }
        }

        // ---- online softmax on fragments (row groups = lrm quads) ----
        {
            float mloc0 = -1e30f, mloc1 = -1e30f;
#pragma unroll
            for (int n = 0; n < 8; n++) {
                mloc0 = fmaxf(mloc0, fmaxf(s_frag[n][0], s_frag[n][1]));
                mloc1 = fmaxf(mloc1, fmaxf(s_frag[n][2], s_frag[n][3]));
            }
            mloc0 = fmaxf(mloc0, __shfl_xor_sync(0xffffffffu, mloc0, 1));
            mloc0 = fmaxf(mloc0, __shfl_xor_sync(0xffffffffu, mloc0, 2));
            mloc1 = fmaxf(mloc1, __shfl_xor_sync(0xffffffffu, mloc1, 1));
            mloc1 = fmaxf(mloc1, __shfl_xor_sync(0xffffffffu, mloc1, 2));
            float mn0 = fmaxf(m0, mloc0), mn1 = fmaxf(m1, mloc1);
            float c0 = __expf(m0 - mn0), c1 = __expf(m1 - mn1);
            float ps0 = 0.f, ps1 = 0.f;
#pragma unroll
            for (int n = 0; n < 8; n++) {
                float p0 = __expf(s_frag[n][0] - mn0);
                float p1 = __expf(s_frag[n][1] - mn0);
                float p2 = __expf(s_frag[n][2] - mn1);
                float p3 = __expf(s_frag[n][3] - mn1);
                s_frag[n][0] = p0; s_frag[n][1] = p1;
                s_frag[n][2] = p2; s_frag[n][3] = p3;
                ps0 += p0 + p1; ps1 += p2 + p3;
            }
            ps0 += __shfl_xor_sync(0xffffffffu, ps0, 1);
            ps0 += __shfl_xor_sync(0xffffffffu, ps0, 2);
            ps1 += __shfl_xor_sync(0xffffffffu, ps1, 1);
            ps1 += __shfl_xor_sync(0xffffffffu, ps1, 2);
            l0 = l0 * c0 + ps0; m0 = mn0;
            l1 = l1 * c1 + ps1; m1 = mn1;
#pragma unroll
            for (int n = 0; n < 8; n++) {
                o_frag[n][0] *= c0; o_frag[n][1] *= c0;
                o_frag[n][2] *= c1; o_frag[n][3] *= c1;
            }
        }

        // ---- write P (tf32) to smem; own-warp rows only -> syncwarp ----
#pragma unroll
        for (int n = 0; n < 8; n++) {
            uint2 p01; p01.x = f2tf(s_frag[n][0]); p01.y = f2tf(s_frag[n][1]);
            *(uint2*)&sP[(rowA + lq) * FSTR + 8 * n + 2 * lrm] = p01;
            uint2 p23; p23.x = f2tf(s_frag[n][2]); p23.y = f2tf(s_frag[n][3]);
            *(uint2*)&sP[(rowA + lq + 8) * FSTR + 8 * n + 2 * lrm] = p23;
        }
        __syncwarp();

        // ---- O += P V via mma (B operand = V^T from sVt) ----
#pragma unroll
        for (int ks = 0; ks < 64; ks += 8) {
            uint32_t af[4];
            af[0] = sP[(rowA + lq) * FSTR + ks + lrm];
            af[1] = sP[(rowA + lq + 8) * FSTR + ks + lrm];
            af[2] = sP[(rowA + lq) * FSTR + ks + lrm + 4];
            af[3] = sP[(rowA + lq + 8) * FSTR + ks + lrm + 4];
#pragma unroll
            for (int n = 0; n < 8; n++) {
                uint32_t bf[2];
                bf[0] = sVt[(8 * n + lq) * FSTR + ks + lrm];
                bf[1] = sVt[(8 * n + lq) * FSTR + ks + lrm + 4];
                mma_tf32(o_frag[n], af, bf);
            }
        }
    }

    // ---- epilogue ----
    float i0 = 1.0f / l0, i1 = 1.0f / l1;
    float* d0 = O + base + (size_t)(q0 + rowA + lq) * DIM;
    float* d1 = O + base + (size_t)(q0 + rowA + lq + 8) * DIM;
#pragma unroll
    for (int n = 0; n < 8; n++) {
        int col = 8 * n + 2 * lrm;
        float2 w0; w0.x = o_frag[n][0] * i0; w0.y = o_frag[n][1] * i0;
        float2 w1; w1.x = o_frag[n][2] * i1; w1.y = o_frag[n][3] * i1;
        *(float2*)&d0[col] = w0;
        *(float2*)&d1[col] = w1;
    }
}

// ---------------------------------------------------------------------------
extern "C" void kernel_launch(void* const* d_in, const int* in_sizes, int n_in,
                              void* d_out, int out_size) {
    const float* x  = (const float*)d_in[0];
    const float* g1 = (const float*)d_in[1];
    const float* b1 = (const float*)d_in[2];
    const float* Wq = (const float*)d_in[3];
    const float* bq = (const float*)d_in[4];
    const float* Wk = (const float*)d_in[5];
    const float* bk = (const float*)d_in[6];
    const float* Wv = (const float*)d_in[7];
    const float* bv = (const float*)d_in[8];
    const float* Wo = (const float*)d_in[9];
    const float* bo = (const float*)d_in[10];
    float* out = (float*)d_out;

    float *h_p, *q_p, *k_p, *v_p, *a_p;
    cudaGetSymbolAddress((void**)&h_p, g_h);
    cudaGetSymbolAddress((void**)&q_p, g_q);
    cudaGetSymbolAddress((void**)&k_p, g_k);
    cudaGetSymbolAddress((void**)&v_p, g_v);
    cudaGetSymbolAddress((void**)&a_p, g_att);

    // smem: (QT + 64 + 64 + QT) * FSTR words
    const int attn_smem = (QT + 64 + 64 + QT) * FSTR * (int)sizeof(uint32_t); // 104448
    cudaFuncSetAttribute(attn_kernel, cudaFuncAttributeMaxDynamicSharedMemorySize,
                         attn_smem);

    ln_kernel<<<BT, 256>>>(x, g1, b1, h_p);

    dim3 qkv_grid(DIM / 128, BT / 128, 3);
    gemm_qkv<<<qkv_grid, 256>>>(h_p, Wq, bq, q_p, Wk, bk, k_p, Wv, bv, v_p,
                                BT, DIM, DIM);

    attn_kernel<<<dim3(TSEQ / QT, NH, 2), 256, attn_smem>>>(q_p, k_p, v_p, a_p);

    dim3 ggrid(DIM / 128, BT / 128);
    gemm_tf32<<<ggrid, 256>>>(a_p, Wo, bo, out, BT, DIM, DIM);
}